// round 2
// baseline (speedup 1.0000x reference)
#include <cuda_runtime.h>
#include <math.h>

// ---------------- problem dims ----------------
#define B_   64
#define L_   256
#define T_   32
#define E_   384
#define H_   6
#define HD_  64
#define DI_  768
#define DS_  16
#define DC_  4
#define DR_  24
#define HID_ 1536
#define V_   97
#define ND_  12
#define EPS_ 1e-5f
#define M_   (B_ * T_)     /* 2048 */
#define ML_  (B_ * L_)     /* 16384 */
#define DBL_ (DR_ + 2 * DS_) /* 56 */

// ---------------- scratch (device globals; no runtime alloc) ----------------
__device__ float g_hidden[M_ * E_];
__device__ float g_resid [M_ * E_];
__device__ float g_xz    [M_ * 2 * DI_];
__device__ float g_xc    [M_ * DI_];
__device__ float g_dbl   [M_ * DBL_];
__device__ float g_dt    [M_ * DI_];
__device__ float g_y     [M_ * DI_];
__device__ float g_qh    [M_ * E_];
__device__ float g_kh    [ML_ * E_];
__device__ float g_vh    [ML_ * E_];
__device__ float g_ctx   [M_ * E_];
__device__ float g_ffn   [M_ * HID_];

// ---------------- init: hidden = query_embed + pos_emb; resid = 0 ----------------
__global__ void init_kernel(const float* __restrict__ qe, const float* __restrict__ pe)
{
    int idx = blockIdx.x * blockDim.x + threadIdx.x;
    if (idx < M_ * E_) {
        int te = idx % (T_ * E_);
        g_hidden[idx] = qe[te] + pe[te];
        g_resid[idx]  = 0.f;
    }
}

// ---------------- fused: resid += hidden; hidden = rmsnorm(resid)*w ----------------
__global__ void __launch_bounds__(128) add_rmsnorm_kernel(const float* __restrict__ w)
{
    int row = blockIdx.x;
    int tid = threadIdx.x;
    __shared__ float sh[4];
    float v[3];
    float ss = 0.f;
#pragma unroll
    for (int i = 0; i < 3; i++) {
        int e = tid + i * 128;
        float x = g_hidden[row * E_ + e] + g_resid[row * E_ + e];
        g_resid[row * E_ + e] = x;
        v[i] = x;
        ss += x * x;
    }
#pragma unroll
    for (int o = 16; o > 0; o >>= 1) ss += __shfl_xor_sync(0xffffffffu, ss, o);
    if ((tid & 31) == 0) sh[tid >> 5] = ss;
    __syncthreads();
    float tot = sh[0] + sh[1] + sh[2] + sh[3];
    float scale = rsqrtf(tot / (float)E_ + EPS_);
#pragma unroll
    for (int i = 0; i < 3; i++) {
        int e = tid + i * 128;
        g_hidden[row * E_ + e] = v[i] * scale * w[e];
    }
}

// ---------------- layernorm: hidden = LN(resid)*w + b ----------------
__global__ void __launch_bounds__(128) layernorm_kernel(const float* __restrict__ w,
                                                        const float* __restrict__ bb)
{
    int row = blockIdx.x;
    int tid = threadIdx.x;
    __shared__ float sh[4];
    float v[3];
    float s = 0.f;
#pragma unroll
    for (int i = 0; i < 3; i++) {
        int e = tid + i * 128;
        v[i] = g_resid[row * E_ + e];
        s += v[i];
    }
#pragma unroll
    for (int o = 16; o > 0; o >>= 1) s += __shfl_xor_sync(0xffffffffu, s, o);
    if ((tid & 31) == 0) sh[tid >> 5] = s;
    __syncthreads();
    float mu = (sh[0] + sh[1] + sh[2] + sh[3]) / (float)E_;
    __syncthreads();
    float s2 = 0.f;
#pragma unroll
    for (int i = 0; i < 3; i++) {
        float d = v[i] - mu;
        s2 += d * d;
    }
#pragma unroll
    for (int o = 16; o > 0; o >>= 1) s2 += __shfl_xor_sync(0xffffffffu, s2, o);
    if ((tid & 31) == 0) sh[tid >> 5] = s2;
    __syncthreads();
    float var = (sh[0] + sh[1] + sh[2] + sh[3]) / (float)E_;
    float scale = rsqrtf(var + EPS_);
#pragma unroll
    for (int i = 0; i < 3; i++) {
        int e = tid + i * 128;
        g_hidden[row * E_ + e] = (v[i] - mu) * scale * w[e] + bb[e];
    }
}

// ---------------- generic fp32 GEMM: C[M,N] = A[M,K] @ W[N,K]^T (+bias)(+epi) ----------------
// EPI: 0 = none, 1 = relu, 2 = accumulate into C (residual add)
template <int EPI>
__global__ void __launch_bounds__(256) gemm_kernel(const float* __restrict__ A,
                                                   const float* __restrict__ W,
                                                   const float* __restrict__ bias,
                                                   float* __restrict__ C,
                                                   int M, int N, int K)
{
    const int BM = 64, BN = 64, BK = 16;
    __shared__ float As[BK][BM];
    __shared__ float Bs[BK][BN];
    int tid = threadIdx.x;
    int tx = tid & 15, ty = tid >> 4;
    int rowBase = blockIdx.y * BM, colBase = blockIdx.x * BN;
    float acc[4][4] = {};

    for (int k0 = 0; k0 < K; k0 += BK) {
#pragma unroll
        for (int i = 0; i < 4; i++) {
            int idx = tid + i * 256;
            int k = idx & 15, m = idx >> 4;
            int gr = rowBase + m, gc = k0 + k;
            As[k][m] = (gr < M && gc < K) ? A[(long)gr * K + gc] : 0.f;
        }
#pragma unroll
        for (int i = 0; i < 4; i++) {
            int idx = tid + i * 256;
            int k = idx & 15, nn = idx >> 4;
            int gr = colBase + nn, gc = k0 + k;
            Bs[k][nn] = (gr < N && gc < K) ? W[(long)gr * K + gc] : 0.f;
        }
        __syncthreads();
#pragma unroll
        for (int kk = 0; kk < BK; kk++) {
            float4 av = *reinterpret_cast<const float4*>(&As[kk][ty * 4]);
            float4 bv = *reinterpret_cast<const float4*>(&Bs[kk][tx * 4]);
            float a[4] = {av.x, av.y, av.z, av.w};
            float b[4] = {bv.x, bv.y, bv.z, bv.w};
#pragma unroll
            for (int i = 0; i < 4; i++)
#pragma unroll
                for (int j = 0; j < 4; j++)
                    acc[i][j] = fmaf(a[i], b[j], acc[i][j]);
        }
        __syncthreads();
    }

#pragma unroll
    for (int i = 0; i < 4; i++) {
        int r = rowBase + ty * 4 + i;
        if (r >= M) continue;
#pragma unroll
        for (int j = 0; j < 4; j++) {
            int c = colBase + tx * 4 + j;
            if (c >= N) continue;
            float v = acc[i][j] + (bias ? bias[c] : 0.f);
            if (EPI == 1) v = fmaxf(v, 0.f);
            if (EPI == 2) v += C[(long)r * N + c];
            C[(long)r * N + c] = v;
        }
    }
}

// ---------------- causal depthwise conv (DC=4) + bias + silu ----------------
__global__ void conv_silu_kernel(const float* __restrict__ cw, const float* __restrict__ cb)
{
    int idx = blockIdx.x * blockDim.x + threadIdx.x;
    if (idx >= M_ * DI_) return;
    int d = idx % DI_;
    int bt = idx / DI_;
    int t = bt % T_;
    float acc = cb[d];
    const float* w = &cw[d * DC_];
#pragma unroll
    for (int k = 0; k < DC_; k++) {
        int tt = t - (DC_ - 1) + k;
        if (tt >= 0) acc = fmaf(w[k], g_xz[(long)(bt - t + tt) * 2 * DI_ + d], acc);
    }
    float sig = 1.f / (1.f + __expf(-acc));
    g_xc[idx] = acc * sig;
}

// ---------------- dt = softplus(dbl[:, :DR] @ dt_w^T + dt_b) ----------------
__global__ void __launch_bounds__(256) dt_kernel(const float* __restrict__ dtw,
                                                 const float* __restrict__ dtb)
{
    int row = blockIdx.x;
    int tid = threadIdx.x;
    __shared__ float dr[DR_];
    if (tid < DR_) dr[tid] = g_dbl[row * DBL_ + tid];
    __syncthreads();
#pragma unroll
    for (int c = 0; c < 3; c++) {
        int d = c * 256 + tid;
        float acc = dtb[d];
        const float* w = &dtw[d * DR_];
#pragma unroll
        for (int r = 0; r < DR_; r++) acc = fmaf(dr[r], w[r], acc);
        float sp = (acc > 20.f) ? acc : log1pf(__expf(acc));
        g_dt[row * DI_ + d] = sp;
    }
}

// ---------------- selective scan + D-skip + silu(z) gate ----------------
// grid (DI_/256, B_), one thread per (b, d) lane; B/C broadcast via shared.
__global__ void __launch_bounds__(256) scan_kernel(const float* __restrict__ Alog,
                                                   const float* __restrict__ Dp)
{
    int b = blockIdx.y;
    int tid = threadIdx.x;
    int d = blockIdx.x * 256 + tid;
    __shared__ float Bs[DS_], Cs[DS_];
    float Av[DS_], h[DS_];
#pragma unroll
    for (int s = 0; s < DS_; s++) {
        Av[s] = -__expf(Alog[d * DS_ + s]);  // A = -exp(Alog)  (negative)
        h[s] = 0.f;
    }
    float Dv = Dp[d];
    for (int t = 0; t < T_; t++) {
        int row = b * T_ + t;
        if (tid < DS_)           Bs[tid]       = g_dbl[row * DBL_ + DR_ + tid];
        else if (tid < 2 * DS_)  Cs[tid - DS_] = g_dbl[row * DBL_ + DR_ + DS_ + (tid - DS_)];
        __syncthreads();
        float dtv = g_dt[row * DI_ + d];
        float xcv = g_xc[row * DI_ + d];
        float zv  = g_xz[(long)row * 2 * DI_ + DI_ + d];
        float dtx = dtv * xcv;
        float y = 0.f;
#pragma unroll
        for (int s = 0; s < DS_; s++) {
            float dA = __expf(dtv * Av[s]);
            h[s] = fmaf(dA, h[s], dtx * Bs[s]);
            y = fmaf(h[s], Cs[s], y);
        }
        y = fmaf(Dv, xcv, y);
        float sig = 1.f / (1.f + __expf(-zv));
        g_y[row * DI_ + d] = y * zv * sig;
        __syncthreads();
    }
}

// ---------------- attention: block per (h, b), loop t; scores+softmax+ctx ----------------
__global__ void __launch_bounds__(256) attn_kernel()
{
    int h = blockIdx.x;
    int b = blockIdx.y;
    int tid = threadIdx.x;
    __shared__ float qsh[T_ * HD_];   // 8KB
    __shared__ float p[L_];
    __shared__ float red[8];
    __shared__ float accs[4 * HD_];
    __shared__ float s_mx, s_inv;

#pragma unroll
    for (int i = 0; i < 8; i++) {
        int idx = tid + i * 256;      // idx = t*64 + d
        int t = idx >> 6, d = idx & 63;
        qsh[idx] = g_qh[(long)(b * T_ + t) * E_ + h * HD_ + d];
    }
    __syncthreads();

    const float* kr = &g_kh[((long)b * L_ + tid) * E_ + h * HD_];
    const float* vb = &g_vh[((long)b * L_) * E_ + h * HD_];
    int lane = tid & 31, wid = tid >> 5;
    int dd = tid & 63, grp = tid >> 6;

    for (int t = 0; t < T_; t++) {
        const float* qr = &qsh[t * HD_];
        float sc = 0.f;
#pragma unroll
        for (int d = 0; d < HD_; d++) sc = fmaf(qr[d], kr[d], sc);
        sc *= 0.125f;  // 1/sqrt(64)

        float m = sc;
#pragma unroll
        for (int o = 16; o > 0; o >>= 1) m = fmaxf(m, __shfl_xor_sync(0xffffffffu, m, o));
        if (lane == 0) red[wid] = m;
        __syncthreads();
        if (tid == 0) {
            float mm = red[0];
#pragma unroll
            for (int i = 1; i < 8; i++) mm = fmaxf(mm, red[i]);
            s_mx = mm;
        }
        __syncthreads();
        float e = __expf(sc - s_mx);
        p[tid] = e;
        float ss = e;
#pragma unroll
        for (int o = 16; o > 0; o >>= 1) ss += __shfl_xor_sync(0xffffffffu, ss, o);
        if (lane == 0) red[wid] = ss;
        __syncthreads();
        if (tid == 0) {
            float s = 0.f;
#pragma unroll
            for (int i = 0; i < 8; i++) s += red[i];
            s_inv = 1.f / s;
        }
        __syncthreads();

        // ctx: 4 groups of 64 threads, each sums 64 source positions
        float part = 0.f;
        const float* vrow = vb + (long)(grp * 64) * E_ + dd;
#pragma unroll
        for (int s = 0; s < 64; s++) part = fmaf(p[grp * 64 + s], vrow[(long)s * E_], part);
        accs[grp * HD_ + dd] = part;
        __syncthreads();
        if (tid < HD_) {
            float v = (accs[tid] + accs[HD_ + tid] + accs[2 * HD_ + tid] + accs[3 * HD_ + tid]) * s_inv;
            g_ctx[(long)(b * T_ + t) * E_ + h * HD_ + tid] = v;
        }
        __syncthreads();
    }
}

// ---------------- host: full pipeline (graph-capturable; kernels only) ----------------
static inline dim3 gemm_grid(int M, int N) { return dim3((N + 63) / 64, (M + 63) / 64); }

extern "C" void kernel_launch(void* const* d_in, const int* in_sizes, int n_in,
                              void* d_out, int out_size)
{
    (void)in_sizes; (void)n_in; (void)out_size;
    const float* enc      = (const float*)d_in[0];
    const float* qe       = (const float*)d_in[1];
    const float* pe       = (const float*)d_in[2];
    const float* m_norm_w = (const float*)d_in[3];
    const float* m_in_w   = (const float*)d_in[4];
    const float* m_conv_w = (const float*)d_in[5];
    const float* m_conv_b = (const float*)d_in[6];
    const float* m_xproj_w= (const float*)d_in[7];
    const float* m_dt_w   = (const float*)d_in[8];
    const float* m_dt_b   = (const float*)d_in[9];
    const float* m_Alog   = (const float*)d_in[10];
    const float* m_D      = (const float*)d_in[11];
    const float* m_out_w  = (const float*)d_in[12];
    const float* rms_w    = (const float*)d_in[13];
    const float* wq = (const float*)d_in[14];
    const float* bq = (const float*)d_in[15];
    const float* wk = (const float*)d_in[16];
    const float* bk = (const float*)d_in[17];
    const float* wv = (const float*)d_in[18];
    const float* bv = (const float*)d_in[19];
    const float* wo = (const float*)d_in[20];
    const float* bo = (const float*)d_in[21];
    const float* ln1_w = (const float*)d_in[22];
    const float* ln1_b = (const float*)d_in[23];
    const float* ffn_w1 = (const float*)d_in[24];
    const float* ffn_b1 = (const float*)d_in[25];
    const float* ffn_w2 = (const float*)d_in[26];
    const float* ffn_b2 = (const float*)d_in[27];
    const float* ln2_w = (const float*)d_in[28];
    const float* ln2_b = (const float*)d_in[29];
    const float* out_w = (const float*)d_in[30];
    const float* out_b = (const float*)d_in[31];
    float* out = (float*)d_out;

    // resolve scratch addresses (host API, not captured, cheap)
    float *p_hidden, *p_xz, *p_xc, *p_dbl, *p_y, *p_qh, *p_kh, *p_vh, *p_ctx, *p_ffn, *p_resid;
    cudaGetSymbolAddress((void**)&p_hidden, g_hidden);
    cudaGetSymbolAddress((void**)&p_resid,  g_resid);
    cudaGetSymbolAddress((void**)&p_xz,     g_xz);
    cudaGetSymbolAddress((void**)&p_xc,     g_xc);
    cudaGetSymbolAddress((void**)&p_dbl,    g_dbl);
    cudaGetSymbolAddress((void**)&p_y,      g_y);
    cudaGetSymbolAddress((void**)&p_qh,     g_qh);
    cudaGetSymbolAddress((void**)&p_kh,     g_kh);
    cudaGetSymbolAddress((void**)&p_vh,     g_vh);
    cudaGetSymbolAddress((void**)&p_ctx,    g_ctx);
    cudaGetSymbolAddress((void**)&p_ffn,    g_ffn);

    init_kernel<<<(M_ * E_ + 255) / 256, 256>>>(qe, pe);

    for (int n = 0; n < ND_; n++) {
        add_rmsnorm_kernel<<<M_, 128>>>(m_norm_w + n * E_);
        // xz = hidden @ in_w^T           [2048, 1536, K=384]
        gemm_kernel<0><<<gemm_grid(M_, 2 * DI_), 256>>>(p_hidden, m_in_w + (long)n * 2 * DI_ * E_,
                                                        nullptr, p_xz, M_, 2 * DI_, E_);
        conv_silu_kernel<<<(M_ * DI_ + 255) / 256, 256>>>(m_conv_w + (long)n * DI_ * DC_,
                                                          m_conv_b + n * DI_);
        // dbl = xc @ xproj_w^T           [2048, 56, K=768]
        gemm_kernel<0><<<gemm_grid(M_, DBL_), 256>>>(p_xc, m_xproj_w + (long)n * DBL_ * DI_,
                                                     nullptr, p_dbl, M_, DBL_, DI_);
        dt_kernel<<<M_, 256>>>(m_dt_w + (long)n * DI_ * DR_, m_dt_b + n * DI_);
        scan_kernel<<<dim3(DI_ / 256, B_), 256>>>(m_Alog + (long)n * DI_ * DS_, m_D + n * DI_);
        // hidden = y @ out_w^T           [2048, 384, K=768]
        gemm_kernel<0><<<gemm_grid(M_, E_), 256>>>(p_y, m_out_w + (long)n * E_ * DI_,
                                                   nullptr, p_hidden, M_, E_, DI_);
    }

    // final pre-attention norm
    add_rmsnorm_kernel<<<M_, 128>>>(rms_w);

    // projections
    gemm_kernel<0><<<gemm_grid(M_,  E_), 256>>>(p_hidden, wq, bq, p_qh, M_,  E_, E_);
    gemm_kernel<0><<<gemm_grid(ML_, E_), 256>>>(enc,      wk, bk, p_kh, ML_, E_, E_);
    gemm_kernel<0><<<gemm_grid(ML_, E_), 256>>>(enc,      wv, bv, p_vh, ML_, E_, E_);

    attn_kernel<<<dim3(H_, B_), 256>>>();

    // resid += ctx @ wo^T + bo
    gemm_kernel<2><<<gemm_grid(M_, E_), 256>>>(p_ctx, wo, bo, p_resid, M_, E_, E_);

    layernorm_kernel<<<M_, 128>>>(ln1_w, ln1_b);
    gemm_kernel<1><<<gemm_grid(M_, HID_), 256>>>(p_hidden, ffn_w1, ffn_b1, p_ffn, M_, HID_, E_);
    gemm_kernel<2><<<gemm_grid(M_, E_), 256>>>(p_ffn, ffn_w2, ffn_b2, p_resid, M_, E_, HID_);
    layernorm_kernel<<<M_, 128>>>(ln2_w, ln2_b);

    // logits = hidden @ out_w^T + out_b   [2048, 97, K=384]
    gemm_kernel<0><<<gemm_grid(M_, V_), 256>>>(p_hidden, out_w, out_b, out, M_, V_, E_);
}

// round 3
// speedup vs baseline: 1.6986x; 1.6986x over previous
#include <cuda_runtime.h>
#include <math.h>

// ---------------- problem dims ----------------
#define B_   64
#define L_   256
#define T_   32
#define E_   384
#define H_   6
#define HD_  64
#define DI_  768
#define DS_  16
#define DC_  4
#define DR_  24
#define HID_ 1536
#define V_   97
#define ND_  12
#define EPS_ 1e-5f
#define M_   (B_ * T_)     /* 2048 */
#define ML_  (B_ * L_)     /* 16384 */
#define DBL_ (DR_ + 2 * DS_) /* 56 */
#define SPK_ 6             /* split-K factor for xproj */

// ---------------- scratch (device globals; no runtime alloc) ----------------
__device__ float g_hidden[M_ * E_];
__device__ float g_resid [M_ * E_];
__device__ float g_xz    [M_ * 2 * DI_];
__device__ float g_xc    [M_ * DI_];
__device__ float g_dbl   [M_ * DBL_];
__device__ float g_dblp  [SPK_ * M_ * DBL_];
__device__ float g_dt    [M_ * DI_];
__device__ float g_y     [M_ * DI_];
__device__ float g_qh    [M_ * E_];
__device__ float g_kh    [ML_ * E_];
__device__ float g_vh    [ML_ * E_];
__device__ float g_ctx   [M_ * E_];
__device__ float g_ffn   [M_ * HID_];

// ---------------- init ----------------
__global__ void init_kernel(const float* __restrict__ qe, const float* __restrict__ pe)
{
    int idx = blockIdx.x * blockDim.x + threadIdx.x;
    if (idx < M_ * E_) {
        int te = idx % (T_ * E_);
        g_hidden[idx] = qe[te] + pe[te];
        g_resid[idx]  = 0.f;
    }
}

// ---------------- fused: resid += hidden; hidden = rmsnorm(resid)*w ----------------
__global__ void __launch_bounds__(128) add_rmsnorm_kernel(const float* __restrict__ w)
{
    int row = blockIdx.x;
    int tid = threadIdx.x;
    __shared__ float sh[4];
    float v[3];
    float ss = 0.f;
#pragma unroll
    for (int i = 0; i < 3; i++) {
        int e = tid + i * 128;
        float x = g_hidden[row * E_ + e] + g_resid[row * E_ + e];
        g_resid[row * E_ + e] = x;
        v[i] = x;
        ss += x * x;
    }
#pragma unroll
    for (int o = 16; o > 0; o >>= 1) ss += __shfl_xor_sync(0xffffffffu, ss, o);
    if ((tid & 31) == 0) sh[tid >> 5] = ss;
    __syncthreads();
    float tot = sh[0] + sh[1] + sh[2] + sh[3];
    float scale = rsqrtf(tot / (float)E_ + EPS_);
#pragma unroll
    for (int i = 0; i < 3; i++) {
        int e = tid + i * 128;
        g_hidden[row * E_ + e] = v[i] * scale * w[e];
    }
}

// ---------------- layernorm ----------------
__global__ void __launch_bounds__(128) layernorm_kernel(const float* __restrict__ w,
                                                        const float* __restrict__ bb)
{
    int row = blockIdx.x;
    int tid = threadIdx.x;
    __shared__ float sh[4];
    float v[3];
    float s = 0.f;
#pragma unroll
    for (int i = 0; i < 3; i++) {
        int e = tid + i * 128;
        v[i] = g_resid[row * E_ + e];
        s += v[i];
    }
#pragma unroll
    for (int o = 16; o > 0; o >>= 1) s += __shfl_xor_sync(0xffffffffu, s, o);
    if ((tid & 31) == 0) sh[tid >> 5] = s;
    __syncthreads();
    float mu = (sh[0] + sh[1] + sh[2] + sh[3]) / (float)E_;
    __syncthreads();
    float s2 = 0.f;
#pragma unroll
    for (int i = 0; i < 3; i++) {
        float d = v[i] - mu;
        s2 += d * d;
    }
#pragma unroll
    for (int o = 16; o > 0; o >>= 1) s2 += __shfl_xor_sync(0xffffffffu, s2, o);
    if ((tid & 31) == 0) sh[tid >> 5] = s2;
    __syncthreads();
    float var = (sh[0] + sh[1] + sh[2] + sh[3]) / (float)E_;
    float scale = rsqrtf(var + EPS_);
#pragma unroll
    for (int i = 0; i < 3; i++) {
        int e = tid + i * 128;
        g_hidden[row * E_ + e] = (v[i] - mu) * scale * w[e] + bb[e];
    }
}

// ================= fast double-buffered SGEMM =================
// C[M,N] = A[M,K] @ W[N,K]^T (+bias)(+epi); requires BM|M, BN|N, 16|K.
// EPI: 0 none, 1 relu, 2 accumulate into C.
template <int BM, int BN>
__device__ __forceinline__ void stsm_tile(float (*As)[BM + 4], float (*Bs)[BN + 4],
                                          const float4* ra, const float4* rb,
                                          int lkq, int lrow)
{
    constexpr int RG = BM / 64, CG = BN / 64;
#pragma unroll
    for (int g = 0; g < RG; g++) {
        As[lkq + 0][g * 64 + lrow] = ra[g].x;
        As[lkq + 1][g * 64 + lrow] = ra[g].y;
        As[lkq + 2][g * 64 + lrow] = ra[g].z;
        As[lkq + 3][g * 64 + lrow] = ra[g].w;
    }
#pragma unroll
    for (int g = 0; g < CG; g++) {
        Bs[lkq + 0][g * 64 + lrow] = rb[g].x;
        Bs[lkq + 1][g * 64 + lrow] = rb[g].y;
        Bs[lkq + 2][g * 64 + lrow] = rb[g].z;
        Bs[lkq + 3][g * 64 + lrow] = rb[g].w;
    }
}

template <int BM, int BN, int EPI>
__global__ void __launch_bounds__(256) gemm_db(const float* __restrict__ A,
                                               const float* __restrict__ W,
                                               const float* __restrict__ bias,
                                               float* __restrict__ C,
                                               int M, int N, int K)
{
    constexpr int RG = BM / 64, CG = BN / 64;
    __shared__ float As[2][16][BM + 4];
    __shared__ float Bs[2][16][BN + 4];
    int tid = threadIdx.x;
    int rowBase = blockIdx.y * BM, colBase = blockIdx.x * BN;
    int lrow = tid >> 2;            // 0..63
    int lkq  = (tid & 3) * 4;

    const float* Ap = A + (long)(rowBase + lrow) * K + lkq;
    const float* Wp = W + (long)(colBase + lrow) * K + lkq;

    float4 ra[RG], rb[CG];
#pragma unroll
    for (int g = 0; g < RG; g++) ra[g] = *(const float4*)(Ap + (long)g * 64 * K);
#pragma unroll
    for (int g = 0; g < CG; g++) rb[g] = *(const float4*)(Wp + (long)g * 64 * K);
    stsm_tile<BM, BN>(As[0], Bs[0], ra, rb, lkq, lrow);
    __syncthreads();

    int tx = tid & 15, ty = tid >> 4;
    int tx4 = tx * 4, ty4 = ty * 4;
    float acc[RG * 4][CG * 4] = {};
    int buf = 0;
    int nt = K / 16;

    for (int t = 0; t < nt; t++) {
        if (t + 1 < nt) {
            Ap += 16; Wp += 16;
#pragma unroll
            for (int g = 0; g < RG; g++) ra[g] = *(const float4*)(Ap + (long)g * 64 * K);
#pragma unroll
            for (int g = 0; g < CG; g++) rb[g] = *(const float4*)(Wp + (long)g * 64 * K);
        }
        float (*Acur)[BM + 4] = As[buf];
        float (*Bcur)[BN + 4] = Bs[buf];
#pragma unroll
        for (int kk = 0; kk < 16; kk++) {
            float a[RG * 4], b[CG * 4];
#pragma unroll
            for (int g = 0; g < RG; g++) {
                float4 v = *(const float4*)&Acur[kk][g * 64 + ty4];
                a[g * 4 + 0] = v.x; a[g * 4 + 1] = v.y; a[g * 4 + 2] = v.z; a[g * 4 + 3] = v.w;
            }
#pragma unroll
            for (int g = 0; g < CG; g++) {
                float4 v = *(const float4*)&Bcur[kk][g * 64 + tx4];
                b[g * 4 + 0] = v.x; b[g * 4 + 1] = v.y; b[g * 4 + 2] = v.z; b[g * 4 + 3] = v.w;
            }
#pragma unroll
            for (int i = 0; i < RG * 4; i++)
#pragma unroll
                for (int j = 0; j < CG * 4; j++)
                    acc[i][j] = fmaf(a[i], b[j], acc[i][j]);
        }
        if (t + 1 < nt) {
            stsm_tile<BM, BN>(As[buf ^ 1], Bs[buf ^ 1], ra, rb, lkq, lrow);
            __syncthreads();
            buf ^= 1;
        }
    }

#pragma unroll
    for (int gi = 0; gi < RG; gi++)
#pragma unroll
        for (int i = 0; i < 4; i++) {
            int r = rowBase + gi * 64 + ty4 + i;
            float* crow = C + (long)r * N;
#pragma unroll
            for (int gj = 0; gj < CG; gj++) {
                int c = colBase + gj * 64 + tx4;
                float4 v;
                v.x = acc[gi * 4 + i][gj * 4 + 0];
                v.y = acc[gi * 4 + i][gj * 4 + 1];
                v.z = acc[gi * 4 + i][gj * 4 + 2];
                v.w = acc[gi * 4 + i][gj * 4 + 3];
                if (bias) {
                    v.x += bias[c + 0]; v.y += bias[c + 1];
                    v.z += bias[c + 2]; v.w += bias[c + 3];
                }
                if (EPI == 1) {
                    v.x = fmaxf(v.x, 0.f); v.y = fmaxf(v.y, 0.f);
                    v.z = fmaxf(v.z, 0.f); v.w = fmaxf(v.w, 0.f);
                }
                if (EPI == 2) {
                    float4 o = *(const float4*)&crow[c];
                    v.x += o.x; v.y += o.y; v.z += o.z; v.w += o.w;
                }
                *(float4*)&crow[c] = v;
            }
        }
}

// ---------------- generic predicated 64x64 GEMM (small/odd shapes) ----------------
template <int EPI>
__global__ void __launch_bounds__(256) gemm_kernel(const float* __restrict__ A,
                                                   const float* __restrict__ W,
                                                   const float* __restrict__ bias,
                                                   float* __restrict__ C,
                                                   int M, int N, int K)
{
    const int BM = 64, BN = 64, BK = 16;
    __shared__ float As[BK][BM];
    __shared__ float Bs[BK][BN];
    int tid = threadIdx.x;
    int tx = tid & 15, ty = tid >> 4;
    int rowBase = blockIdx.y * BM, colBase = blockIdx.x * BN;
    float acc[4][4] = {};

    for (int k0 = 0; k0 < K; k0 += BK) {
#pragma unroll
        for (int i = 0; i < 4; i++) {
            int idx = tid + i * 256;
            int k = idx & 15, m = idx >> 4;
            int gr = rowBase + m, gc = k0 + k;
            As[k][m] = (gr < M && gc < K) ? A[(long)gr * K + gc] : 0.f;
        }
#pragma unroll
        for (int i = 0; i < 4; i++) {
            int idx = tid + i * 256;
            int k = idx & 15, nn = idx >> 4;
            int gr = colBase + nn, gc = k0 + k;
            Bs[k][nn] = (gr < N && gc < K) ? W[(long)gr * K + gc] : 0.f;
        }
        __syncthreads();
#pragma unroll
        for (int kk = 0; kk < BK; kk++) {
            float4 av = *reinterpret_cast<const float4*>(&As[kk][ty * 4]);
            float4 bv = *reinterpret_cast<const float4*>(&Bs[kk][tx * 4]);
            float a[4] = {av.x, av.y, av.z, av.w};
            float b[4] = {bv.x, bv.y, bv.z, bv.w};
#pragma unroll
            for (int i = 0; i < 4; i++)
#pragma unroll
                for (int j = 0; j < 4; j++)
                    acc[i][j] = fmaf(a[i], b[j], acc[i][j]);
        }
        __syncthreads();
    }

#pragma unroll
    for (int i = 0; i < 4; i++) {
        int r = rowBase + ty * 4 + i;
        if (r >= M) continue;
#pragma unroll
        for (int j = 0; j < 4; j++) {
            int c = colBase + tx * 4 + j;
            if (c >= N) continue;
            float v = acc[i][j] + (bias ? bias[c] : 0.f);
            if (EPI == 1) v = fmaxf(v, 0.f);
            if (EPI == 2) v += C[(long)r * N + c];
            C[(long)r * N + c] = v;
        }
    }
}

// ---------------- xproj split-K: partials, then reduce ----------------
// part[s][m][n] = xc[m, s*128:(s+1)*128] @ xproj_w[n, s*128:(s+1)*128]^T
__global__ void __launch_bounds__(256) xproj_partial_kernel(const float* __restrict__ A,
                                                            const float* __restrict__ W)
{
    const int BK = 16, KS = DI_ / SPK_; // 128
    __shared__ float As[BK][64];
    __shared__ float Bs[BK][64];
    int tid = threadIdx.x;
    int tx = tid & 15, ty = tid >> 4;
    int rowBase = blockIdx.y * 64;
    int s = blockIdx.z;
    int kbase = s * KS;
    float acc[4][4] = {};

    for (int k0 = 0; k0 < KS; k0 += BK) {
#pragma unroll
        for (int i = 0; i < 4; i++) {
            int idx = tid + i * 256;
            int k = idx & 15, m = idx >> 4;
            As[k][m] = A[(long)(rowBase + m) * DI_ + kbase + k0 + k];
        }
#pragma unroll
        for (int i = 0; i < 4; i++) {
            int idx = tid + i * 256;
            int k = idx & 15, nn = idx >> 4;
            Bs[k][nn] = (nn < DBL_) ? W[(long)nn * DI_ + kbase + k0 + k] : 0.f;
        }
        __syncthreads();
#pragma unroll
        for (int kk = 0; kk < BK; kk++) {
            float4 av = *reinterpret_cast<const float4*>(&As[kk][ty * 4]);
            float4 bv = *reinterpret_cast<const float4*>(&Bs[kk][tx * 4]);
            float a[4] = {av.x, av.y, av.z, av.w};
            float b[4] = {bv.x, bv.y, bv.z, bv.w};
#pragma unroll
            for (int i = 0; i < 4; i++)
#pragma unroll
                for (int j = 0; j < 4; j++)
                    acc[i][j] = fmaf(a[i], b[j], acc[i][j]);
        }
        __syncthreads();
    }

#pragma unroll
    for (int i = 0; i < 4; i++) {
        int r = rowBase + ty * 4 + i;
#pragma unroll
        for (int j = 0; j < 4; j++) {
            int c = tx * 4 + j;
            if (c < DBL_)
                g_dblp[((long)s * M_ + r) * DBL_ + c] = acc[i][j];
        }
    }
}

__global__ void xproj_reduce_kernel()
{
    int idx = blockIdx.x * blockDim.x + threadIdx.x;
    if (idx >= M_ * DBL_) return;
    float v = 0.f;
#pragma unroll
    for (int s = 0; s < SPK_; s++) v += g_dblp[(long)s * M_ * DBL_ + idx];
    g_dbl[idx] = v;
}

// ---------------- causal depthwise conv (DC=4) + bias + silu ----------------
__global__ void conv_silu_kernel(const float* __restrict__ cw, const float* __restrict__ cb)
{
    int idx = blockIdx.x * blockDim.x + threadIdx.x;
    if (idx >= M_ * DI_) return;
    int d = idx % DI_;
    int bt = idx / DI_;
    int t = bt % T_;
    float acc = cb[d];
    const float* w = &cw[d * DC_];
#pragma unroll
    for (int k = 0; k < DC_; k++) {
        int tt = t - (DC_ - 1) + k;
        if (tt >= 0) acc = fmaf(w[k], g_xz[(long)(bt - t + tt) * 2 * DI_ + d], acc);
    }
    float sig = 1.f / (1.f + __expf(-acc));
    g_xc[idx] = acc * sig;
}

// ---------------- dt = softplus(dbl[:, :DR] @ dt_w^T + dt_b) ----------------
__global__ void __launch_bounds__(256) dt_kernel(const float* __restrict__ dtw,
                                                 const float* __restrict__ dtb)
{
    int row = blockIdx.x;
    int tid = threadIdx.x;
    __shared__ float dr[DR_];
    if (tid < DR_) dr[tid] = g_dbl[row * DBL_ + tid];
    __syncthreads();
#pragma unroll
    for (int c = 0; c < 3; c++) {
        int d = c * 256 + tid;
        float acc = dtb[d];
        const float* w = &dtw[d * DR_];
#pragma unroll
        for (int r = 0; r < DR_; r++) acc = fmaf(dr[r], w[r], acc);
        float sp = (acc > 20.f) ? acc : log1pf(__expf(acc));
        g_dt[row * DI_ + d] = sp;
    }
}

// ---------------- selective scan + D-skip + silu(z) gate ----------------
__global__ void __launch_bounds__(256) scan_kernel(const float* __restrict__ Alog,
                                                   const float* __restrict__ Dp)
{
    int b = blockIdx.y;
    int tid = threadIdx.x;
    int d = blockIdx.x * 256 + tid;
    __shared__ float Bs[DS_], Cs[DS_];
    float Av[DS_], h[DS_];
#pragma unroll
    for (int s = 0; s < DS_; s++) {
        Av[s] = -__expf(Alog[d * DS_ + s]);
        h[s] = 0.f;
    }
    float Dv = Dp[d];
    for (int t = 0; t < T_; t++) {
        int row = b * T_ + t;
        if (tid < DS_)           Bs[tid]       = g_dbl[row * DBL_ + DR_ + tid];
        else if (tid < 2 * DS_)  Cs[tid - DS_] = g_dbl[row * DBL_ + DR_ + DS_ + (tid - DS_)];
        __syncthreads();
        float dtv = g_dt[row * DI_ + d];
        float xcv = g_xc[row * DI_ + d];
        float zv  = g_xz[(long)row * 2 * DI_ + DI_ + d];
        float dtx = dtv * xcv;
        float y = 0.f;
#pragma unroll
        for (int s = 0; s < DS_; s++) {
            float dA = __expf(dtv * Av[s]);
            h[s] = fmaf(dA, h[s], dtx * Bs[s]);
            y = fmaf(h[s], Cs[s], y);
        }
        y = fmaf(Dv, xcv, y);
        float sig = 1.f / (1.f + __expf(-zv));
        g_y[row * DI_ + d] = y * zv * sig;
        __syncthreads();
    }
}

// ---------------- attention: block per (h, b), loop t ----------------
__global__ void __launch_bounds__(256) attn_kernel()
{
    int h = blockIdx.x;
    int b = blockIdx.y;
    int tid = threadIdx.x;
    __shared__ float qsh[T_ * HD_];
    __shared__ float p[L_];
    __shared__ float red[8];
    __shared__ float accs[4 * HD_];
    __shared__ float s_mx, s_inv;

#pragma unroll
    for (int i = 0; i < 8; i++) {
        int idx = tid + i * 256;
        int t = idx >> 6, d = idx & 63;
        qsh[idx] = g_qh[(long)(b * T_ + t) * E_ + h * HD_ + d];
    }
    __syncthreads();

    const float* kr = &g_kh[((long)b * L_ + tid) * E_ + h * HD_];
    const float* vb = &g_vh[((long)b * L_) * E_ + h * HD_];
    int lane = tid & 31, wid = tid >> 5;
    int dd = tid & 63, grp = tid >> 6;

    for (int t = 0; t < T_; t++) {
        const float* qr = &qsh[t * HD_];
        float sc = 0.f;
#pragma unroll
        for (int d = 0; d < HD_; d++) sc = fmaf(qr[d], kr[d], sc);
        sc *= 0.125f;

        float m = sc;
#pragma unroll
        for (int o = 16; o > 0; o >>= 1) m = fmaxf(m, __shfl_xor_sync(0xffffffffu, m, o));
        if (lane == 0) red[wid] = m;
        __syncthreads();
        if (tid == 0) {
            float mm = red[0];
#pragma unroll
            for (int i = 1; i < 8; i++) mm = fmaxf(mm, red[i]);
            s_mx = mm;
        }
        __syncthreads();
        float e = __expf(sc - s_mx);
        p[tid] = e;
        float ss = e;
#pragma unroll
        for (int o = 16; o > 0; o >>= 1) ss += __shfl_xor_sync(0xffffffffu, ss, o);
        if (lane == 0) red[wid] = ss;
        __syncthreads();
        if (tid == 0) {
            float s = 0.f;
#pragma unroll
            for (int i = 0; i < 8; i++) s += red[i];
            s_inv = 1.f / s;
        }
        __syncthreads();

        float part = 0.f;
        const float* vrow = vb + (long)(grp * 64) * E_ + dd;
#pragma unroll
        for (int s = 0; s < 64; s++) part = fmaf(p[grp * 64 + s], vrow[(long)s * E_], part);
        accs[grp * HD_ + dd] = part;
        __syncthreads();
        if (tid < HD_) {
            float v = (accs[tid] + accs[HD_ + tid] + accs[2 * HD_ + tid] + accs[3 * HD_ + tid]) * s_inv;
            g_ctx[(long)(b * T_ + t) * E_ + h * HD_ + tid] = v;
        }
        __syncthreads();
    }
}

// ---------------- host ----------------
extern "C" void kernel_launch(void* const* d_in, const int* in_sizes, int n_in,
                              void* d_out, int out_size)
{
    (void)in_sizes; (void)n_in; (void)out_size;
    const float* enc      = (const float*)d_in[0];
    const float* qe       = (const float*)d_in[1];
    const float* pe       = (const float*)d_in[2];
    const float* m_norm_w = (const float*)d_in[3];
    const float* m_in_w   = (const float*)d_in[4];
    const float* m_conv_w = (const float*)d_in[5];
    const float* m_conv_b = (const float*)d_in[6];
    const float* m_xproj_w= (const float*)d_in[7];
    const float* m_dt_w   = (const float*)d_in[8];
    const float* m_dt_b   = (const float*)d_in[9];
    const float* m_Alog   = (const float*)d_in[10];
    const float* m_D      = (const float*)d_in[11];
    const float* m_out_w  = (const float*)d_in[12];
    const float* rms_w    = (const float*)d_in[13];
    const float* wq = (const float*)d_in[14];
    const float* bq = (const float*)d_in[15];
    const float* wk = (const float*)d_in[16];
    const float* bk = (const float*)d_in[17];
    const float* wv = (const float*)d_in[18];
    const float* bv = (const float*)d_in[19];
    const float* wo = (const float*)d_in[20];
    const float* bo = (const float*)d_in[21];
    const float* ln1_w = (const float*)d_in[22];
    const float* ln1_b = (const float*)d_in[23];
    const float* ffn_w1 = (const float*)d_in[24];
    const float* ffn_b1 = (const float*)d_in[25];
    const float* ffn_w2 = (const float*)d_in[26];
    const float* ffn_b2 = (const float*)d_in[27];
    const float* ln2_w = (const float*)d_in[28];
    const float* ln2_b = (const float*)d_in[29];
    const float* out_w = (const float*)d_in[30];
    const float* out_b = (const float*)d_in[31];
    float* out = (float*)d_out;

    float *p_hidden, *p_xz, *p_xc, *p_y, *p_qh, *p_kh, *p_vh, *p_ctx, *p_ffn, *p_resid;
    cudaGetSymbolAddress((void**)&p_hidden, g_hidden);
    cudaGetSymbolAddress((void**)&p_resid,  g_resid);
    cudaGetSymbolAddress((void**)&p_xz,     g_xz);
    cudaGetSymbolAddress((void**)&p_xc,     g_xc);
    cudaGetSymbolAddress((void**)&p_y,      g_y);
    cudaGetSymbolAddress((void**)&p_qh,     g_qh);
    cudaGetSymbolAddress((void**)&p_kh,     g_kh);
    cudaGetSymbolAddress((void**)&p_vh,     g_vh);
    cudaGetSymbolAddress((void**)&p_ctx,    g_ctx);
    cudaGetSymbolAddress((void**)&p_ffn,    g_ffn);

    init_kernel<<<(M_ * E_ + 255) / 256, 256>>>(qe, pe);

    for (int n = 0; n < ND_; n++) {
        add_rmsnorm_kernel<<<M_, 128>>>(m_norm_w + n * E_);
        // xz = hidden @ in_w^T   [2048 x 1536, K=384]  -> 128x128 tiles, 192 CTAs
        gemm_db<128, 128, 0><<<dim3(2 * DI_ / 128, M_ / 128), 256>>>(
            p_hidden, m_in_w + (long)n * 2 * DI_ * E_, nullptr, p_xz, M_, 2 * DI_, E_);
        conv_silu_kernel<<<(M_ * DI_ + 255) / 256, 256>>>(m_conv_w + (long)n * DI_ * DC_,
                                                          m_conv_b + n * DI_);
        // dbl = xc @ xproj_w^T   [2048 x 56, K=768]  -> split-K over 6 chunks
        xproj_partial_kernel<<<dim3(1, M_ / 64, SPK_), 256>>>(p_xc,
            m_xproj_w + (long)n * DBL_ * DI_);
        xproj_reduce_kernel<<<(M_ * DBL_ + 255) / 256, 256>>>();
        dt_kernel<<<M_, 256>>>(m_dt_w + (long)n * DI_ * DR_, m_dt_b + n * DI_);
        scan_kernel<<<dim3(DI_ / 256, B_), 256>>>(m_Alog + (long)n * DI_ * DS_, m_D + n * DI_);
        // hidden = y @ out_w^T   [2048 x 384, K=768]  -> 64x64 tiles, 192 CTAs
        gemm_db<64, 64, 0><<<dim3(E_ / 64, M_ / 64), 256>>>(
            p_y, m_out_w + (long)n * E_ * DI_, nullptr, p_hidden, M_, E_, DI_);
    }

    add_rmsnorm_kernel<<<M_, 128>>>(rms_w);

    gemm_db<64, 64, 0><<<dim3(E_ / 64, M_ / 64), 256>>>(p_hidden, wq, bq, p_qh, M_, E_, E_);
    gemm_db<128, 128, 0><<<dim3(E_ / 128, ML_ / 128), 256>>>(enc, wk, bk, p_kh, ML_, E_, E_);
    gemm_db<128, 128, 0><<<dim3(E_ / 128, ML_ / 128), 256>>>(enc, wv, bv, p_vh, ML_, E_, E_);

    attn_kernel<<<dim3(H_, B_), 256>>>();

    gemm_db<64, 64, 2><<<dim3(E_ / 64, M_ / 64), 256>>>(p_ctx, wo, bo, p_resid, M_, E_, E_);

    layernorm_kernel<<<M_, 128>>>(ln1_w, ln1_b);
    gemm_db<128, 128, 1><<<dim3(HID_ / 128, M_ / 128), 256>>>(p_hidden, ffn_w1, ffn_b1, p_ffn,
                                                              M_, HID_, E_);
    gemm_db<64, 64, 2><<<dim3(E_ / 64, M_ / 64), 256>>>(p_ffn, ffn_w2, ffn_b2, p_resid,
                                                        M_, E_, HID_);
    layernorm_kernel<<<M_, 128>>>(ln2_w, ln2_b);

    gemm_kernel<0><<<dim3((V_ + 63) / 64, M_ / 64), 256>>>(p_hidden, out_w, out_b, out,
                                                           M_, V_, E_);
}

// round 5
// speedup vs baseline: 2.1926x; 1.2909x over previous
#include <cuda_runtime.h>
#include <cuda_bf16.h>
#include <math.h>
#include <stdint.h>

// ---------------- problem dims ----------------
#define B_   64
#define L_   256
#define T_   32
#define E_   384
#define H_   6
#define HD_  64
#define DI_  768
#define DS_  16
#define DC_  4
#define DR_  24
#define HID_ 1536
#define V_   97
#define ND_  12
#define EPS_ 1e-5f
#define M_   (B_ * T_)       /* 2048 */
#define ML_  (B_ * L_)       /* 16384 */
#define DBL_ (DR_ + 2 * DS_) /* 56 */
#define SPK_ 6

// ---------------- fp32 scratch ----------------
__device__ float g_hidden[M_ * E_];
__device__ float g_resid [M_ * E_];
__device__ float g_xz    [M_ * 2 * DI_];
__device__ float g_xc    [M_ * DI_];
__device__ float g_dbl   [M_ * DBL_];
__device__ float g_dblp  [SPK_ * M_ * DBL_];
__device__ float g_dt    [M_ * DI_];
__device__ float g_qh    [M_ * E_];
__device__ float g_kh    [ML_ * E_];
__device__ float g_vh    [ML_ * E_];

// ---------------- bf16 hi/lo scratch (weights converted once per launch) ----------------
__device__ __nv_bfloat16 w_inw_h [ND_ * 2 * DI_ * E_], w_inw_l [ND_ * 2 * DI_ * E_];
__device__ __nv_bfloat16 w_outw_h[ND_ * E_ * DI_],     w_outw_l[ND_ * E_ * DI_];
__device__ __nv_bfloat16 w_q_h[E_ * E_], w_q_l[E_ * E_];
__device__ __nv_bfloat16 w_k_h[E_ * E_], w_k_l[E_ * E_];
__device__ __nv_bfloat16 w_v_h[E_ * E_], w_v_l[E_ * E_];
__device__ __nv_bfloat16 w_o_h[E_ * E_], w_o_l[E_ * E_];
__device__ __nv_bfloat16 w_f1_h[HID_ * E_], w_f1_l[HID_ * E_];
__device__ __nv_bfloat16 w_f2_h[E_ * HID_], w_f2_l[E_ * HID_];
// activations
__device__ __nv_bfloat16 a_hid_h[M_ * E_],   a_hid_l[M_ * E_];
__device__ __nv_bfloat16 a_y_h  [M_ * DI_],  a_y_l  [M_ * DI_];
__device__ __nv_bfloat16 a_ctx_h[M_ * E_],   a_ctx_l[M_ * E_];
__device__ __nv_bfloat16 a_ffn_h[M_ * HID_], a_ffn_l[M_ * HID_];
__device__ __nv_bfloat16 a_enc_h[ML_ * E_],  a_enc_l[ML_ * E_];

// ---------------- helpers ----------------
__device__ __forceinline__ uint32_t smem_u32(const void* p) {
    uint32_t a;
    asm("{ .reg .u64 t; cvta.to.shared.u64 t, %1; cvt.u32.u64 %0, t; }" : "=r"(a) : "l"(p));
    return a;
}
__device__ __forceinline__ uint32_t pack_bf(__nv_bfloat16 a, __nv_bfloat16 b) {
    return ((uint32_t)__bfloat16_as_ushort(b) << 16) | __bfloat16_as_ushort(a);
}
__device__ __forceinline__ void split1(float v, __nv_bfloat16& h, __nv_bfloat16& l) {
    h = __float2bfloat16_rn(v);
    l = __float2bfloat16_rn(v - __bfloat162float(h));
}

#define LDSM4(r0, r1, r2, r3, addr) \
    asm volatile("ldmatrix.sync.aligned.m8n8.x4.shared.b16 {%0,%1,%2,%3}, [%4];" \
                 : "=r"(r0), "=r"(r1), "=r"(r2), "=r"(r3) : "r"(addr))
#define LDSM2(r0, r1, addr) \
    asm volatile("ldmatrix.sync.aligned.m8n8.x2.shared.b16 {%0,%1}, [%2];" \
                 : "=r"(r0), "=r"(r1) : "r"(addr))
#define MMA16816(d, a, b) \
    asm volatile("mma.sync.aligned.m16n8k16.row.col.f32.bf16.bf16.f32 " \
                 "{%0,%1,%2,%3}, {%4,%5,%6,%7}, {%8,%9}, {%0,%1,%2,%3};" \
                 : "+f"((d)[0]), "+f"((d)[1]), "+f"((d)[2]), "+f"((d)[3]) \
                 : "r"((a)[0]), "r"((a)[1]), "r"((a)[2]), "r"((a)[3]), \
                   "r"((b)[0]), "r"((b)[1]))

// ---------------- fp32 -> bf16 hi/lo convert ----------------
__global__ void convert_hl(const float* __restrict__ src, __nv_bfloat16* __restrict__ h,
                           __nv_bfloat16* __restrict__ l, int n4)
{
    int i = blockIdx.x * blockDim.x + threadIdx.x;
    if (i >= n4) return;
    float4 v = ((const float4*)src)[i];
    __nv_bfloat16 h0, h1, h2, h3, l0, l1, l2, l3;
    split1(v.x, h0, l0); split1(v.y, h1, l1);
    split1(v.z, h2, l2); split1(v.w, h3, l3);
    uint2 hp = make_uint2(pack_bf(h0, h1), pack_bf(h2, h3));
    uint2 lp = make_uint2(pack_bf(l0, l1), pack_bf(l2, l3));
    ((uint2*)h)[i] = hp;
    ((uint2*)l)[i] = lp;
}

// ================= HMMA GEMM: C[M,N] = A[M,K] @ W[N,K]^T =================
// BM=128, BK=32, 256 threads, 8 warps (2 in M x 4 in N). Hi/lo fp32-split (3 passes).
// EPI: 0 none(+bias), 2 accumulate into C(+bias), 3 relu -> bf16 hi/lo (Ch/Cl)
#define PADK 40  /* bf16 elems per smem row (32 data + 8 pad) -> 80B */

template <int BN>
__device__ __forceinline__ void stage_sts(__nv_bfloat16* smem, int stageOff,
                                          const uint4* ra_h, const uint4* ra_l,
                                          const uint4* rb_h, const uint4* rb_l, int tid)
{
    __nv_bfloat16* sAh = smem + stageOff;
    __nv_bfloat16* sAl = sAh + 128 * PADK;
    __nv_bfloat16* sBh = sAl + 128 * PADK;
    __nv_bfloat16* sBl = sBh + BN * PADK;
#pragma unroll
    for (int j = 0; j < 2; j++) {
        int lin = tid + j * 256, r = lin >> 2, kc = lin & 3;
        *(uint4*)(sAh + r * PADK + kc * 8) = ra_h[j];
        *(uint4*)(sAl + r * PADK + kc * 8) = ra_l[j];
    }
#pragma unroll
    for (int j = 0; j < BN / 64; j++) {
        int lin = tid + j * 256, r = lin >> 2, kc = lin & 3;
        *(uint4*)(sBh + r * PADK + kc * 8) = rb_h[j];
        *(uint4*)(sBl + r * PADK + kc * 8) = rb_l[j];
    }
}

template <int BN, int EPI>
__global__ void __launch_bounds__(256) mma_gemm(
    const __nv_bfloat16* __restrict__ Ah, const __nv_bfloat16* __restrict__ Al,
    const __nv_bfloat16* __restrict__ Wh, const __nv_bfloat16* __restrict__ Wl,
    const float* __restrict__ bias, float* __restrict__ C,
    __nv_bfloat16* __restrict__ Ch, __nv_bfloat16* __restrict__ Cl,
    int M, int N, int K)
{
    constexpr int NW = BN / 4;       // warp tile N
    constexpr int NT = NW / 8;       // n8 tiles per warp
    constexpr int STAGE = (128 + BN) * PADK * 2;  // bf16 elems per stage (hi+lo)
    extern __shared__ __nv_bfloat16 smem[];
    int tid = threadIdx.x, lane = tid & 31, w = tid >> 5;
    int wm = w >> 2, wn = w & 3;
    int rowBase = blockIdx.y * 128, colBase = blockIdx.x * BN;
    uint32_t sb = smem_u32(smem);

    uint4 ra_h[2], ra_l[2], rb_h[BN / 64], rb_l[BN / 64];

    // load stage 0
#pragma unroll
    for (int j = 0; j < 2; j++) {
        int lin = tid + j * 256, r = lin >> 2, kc = lin & 3;
        ra_h[j] = ((const uint4*)(Ah + (long)(rowBase + r) * K))[kc];
        ra_l[j] = ((const uint4*)(Al + (long)(rowBase + r) * K))[kc];
    }
#pragma unroll
    for (int j = 0; j < BN / 64; j++) {
        int lin = tid + j * 256, r = lin >> 2, kc = lin & 3;
        rb_h[j] = ((const uint4*)(Wh + (long)(colBase + r) * K))[kc];
        rb_l[j] = ((const uint4*)(Wl + (long)(colBase + r) * K))[kc];
    }
    stage_sts<BN>(smem, 0, ra_h, ra_l, rb_h, rb_l, tid);
    __syncthreads();

    float acc[4][NT][4] = {};
    int nt = K >> 5;
    int buf = 0;

    // ldmatrix lane geometry
    int arow = wm * 64 + (lane & 15);
    int acol = (lane >> 4) << 3;
    int brow = wn * NW + (lane & 7);
    int bcol = ((lane >> 3) & 1) << 3;

    for (int t = 0; t < nt; t++) {
        if (t + 1 < nt) {
            int kb = (t + 1) * 32;
#pragma unroll
            for (int j = 0; j < 2; j++) {
                int lin = tid + j * 256, r = lin >> 2, kc = lin & 3;
                ra_h[j] = ((const uint4*)(Ah + (long)(rowBase + r) * K + kb))[kc];
                ra_l[j] = ((const uint4*)(Al + (long)(rowBase + r) * K + kb))[kc];
            }
#pragma unroll
            for (int j = 0; j < BN / 64; j++) {
                int lin = tid + j * 256, r = lin >> 2, kc = lin & 3;
                rb_h[j] = ((const uint4*)(Wh + (long)(colBase + r) * K + kb))[kc];
                rb_l[j] = ((const uint4*)(Wl + (long)(colBase + r) * K + kb))[kc];
            }
        }
        uint32_t sAh = sb + (uint32_t)(buf * STAGE) * 2;
        uint32_t sAl = sAh + 128 * PADK * 2;
        uint32_t sBh = sAl + 128 * PADK * 2;
        uint32_t sBl = sBh + BN * PADK * 2;
#pragma unroll
        for (int ks = 0; ks < 32; ks += 16) {
            uint32_t ah[4][4], al[4][4], bh[NT][2], bl[NT][2];
#pragma unroll
            for (int i = 0; i < 4; i++) {
                uint32_t off = (uint32_t)((arow + i * 16) * PADK + ks + acol) * 2;
                LDSM4(ah[i][0], ah[i][1], ah[i][2], ah[i][3], sAh + off);
                LDSM4(al[i][0], al[i][1], al[i][2], al[i][3], sAl + off);
            }
#pragma unroll
            for (int j = 0; j < NT; j++) {
                uint32_t off = (uint32_t)((brow + j * 8) * PADK + ks + bcol) * 2;
                LDSM2(bh[j][0], bh[j][1], sBh + off);
                LDSM2(bl[j][0], bl[j][1], sBl + off);
            }
#pragma unroll
            for (int i = 0; i < 4; i++)
#pragma unroll
                for (int j = 0; j < NT; j++) {
                    MMA16816(acc[i][j], ah[i], bh[j]);
                    MMA16816(acc[i][j], ah[i], bl[j]);
                    MMA16816(acc[i][j], al[i], bh[j]);
                }
        }
        if (t + 1 < nt) {
            stage_sts<BN>(smem, (buf ^ 1) * STAGE, ra_h, ra_l, rb_h, rb_l, tid);
            __syncthreads();
            buf ^= 1;
        }
    }

    // epilogue
    int lr = lane >> 2, lc = (lane & 3) * 2;
#pragma unroll
    for (int i = 0; i < 4; i++) {
        int r0 = rowBase + wm * 64 + i * 16 + lr;
#pragma unroll
        for (int j = 0; j < NT; j++) {
            int c0 = colBase + wn * NW + j * 8 + lc;
            float v0 = acc[i][j][0], v1 = acc[i][j][1];
            float v2 = acc[i][j][2], v3 = acc[i][j][3];
            if (bias) {
                float b0 = bias[c0], b1 = bias[c0 + 1];
                v0 += b0; v1 += b1; v2 += b0; v3 += b1;
            }
            if (EPI == 2) {
                float2 o0 = *(const float2*)&C[(long)r0 * N + c0];
                float2 o1 = *(const float2*)&C[(long)(r0 + 8) * N + c0];
                v0 += o0.x; v1 += o0.y; v2 += o1.x; v3 += o1.y;
            }
            if (EPI == 3) {
                v0 = fmaxf(v0, 0.f); v1 = fmaxf(v1, 0.f);
                v2 = fmaxf(v2, 0.f); v3 = fmaxf(v3, 0.f);
                __nv_bfloat16 h0, h1, h2, h3, l0, l1, l2, l3;
                split1(v0, h0, l0); split1(v1, h1, l1);
                split1(v2, h2, l2); split1(v3, h3, l3);
                *(uint32_t*)&Ch[(long)r0 * N + c0]       = pack_bf(h0, h1);
                *(uint32_t*)&Cl[(long)r0 * N + c0]       = pack_bf(l0, l1);
                *(uint32_t*)&Ch[(long)(r0 + 8) * N + c0] = pack_bf(h2, h3);
                *(uint32_t*)&Cl[(long)(r0 + 8) * N + c0] = pack_bf(l2, l3);
            } else {
                *(float2*)&C[(long)r0 * N + c0]       = make_float2(v0, v1);
                *(float2*)&C[(long)(r0 + 8) * N + c0] = make_float2(v2, v3);
            }
        }
    }
}

// ---------------- init ----------------
__global__ void init_kernel(const float* __restrict__ qe, const float* __restrict__ pe)
{
    int idx = blockIdx.x * blockDim.x + threadIdx.x;
    if (idx < M_ * E_) {
        int te = idx % (T_ * E_);
        g_hidden[idx] = qe[te] + pe[te];
        g_resid[idx]  = 0.f;
    }
}

// ---------------- fused: resid += hidden; hidden = rmsnorm(resid)*w  (+hi/lo) ----------------
__global__ void __launch_bounds__(128) add_rmsnorm_kernel(const float* __restrict__ w)
{
    int row = blockIdx.x;
    int tid = threadIdx.x;
    __shared__ float sh[4];
    float v[3];
    float ss = 0.f;
#pragma unroll
    for (int i = 0; i < 3; i++) {
        int e = tid + i * 128;
        float x = g_hidden[row * E_ + e] + g_resid[row * E_ + e];
        g_resid[row * E_ + e] = x;
        v[i] = x;
        ss += x * x;
    }
#pragma unroll
    for (int o = 16; o > 0; o >>= 1) ss += __shfl_xor_sync(0xffffffffu, ss, o);
    if ((tid & 31) == 0) sh[tid >> 5] = ss;
    __syncthreads();
    float tot = sh[0] + sh[1] + sh[2] + sh[3];
    float scale = rsqrtf(tot / (float)E_ + EPS_);
#pragma unroll
    for (int i = 0; i < 3; i++) {
        int e = tid + i * 128;
        float hv = v[i] * scale * w[e];
        g_hidden[row * E_ + e] = hv;
        __nv_bfloat16 h, l;
        split1(hv, h, l);
        a_hid_h[row * E_ + e] = h;
        a_hid_l[row * E_ + e] = l;
    }
}

// ---------------- layernorm (+hi/lo) ----------------
__global__ void __launch_bounds__(128) layernorm_kernel(const float* __restrict__ w,
                                                        const float* __restrict__ bb)
{
    int row = blockIdx.x;
    int tid = threadIdx.x;
    __shared__ float sh[4];
    float v[3];
    float s = 0.f;
#pragma unroll
    for (int i = 0; i < 3; i++) {
        int e = tid + i * 128;
        v[i] = g_resid[row * E_ + e];
        s += v[i];
    }
#pragma unroll
    for (int o = 16; o > 0; o >>= 1) s += __shfl_xor_sync(0xffffffffu, s, o);
    if ((tid & 31) == 0) sh[tid >> 5] = s;
    __syncthreads();
    float mu = (sh[0] + sh[1] + sh[2] + sh[3]) / (float)E_;
    __syncthreads();
    float s2 = 0.f;
#pragma unroll
    for (int i = 0; i < 3; i++) {
        float d = v[i] - mu;
        s2 += d * d;
    }
#pragma unroll
    for (int o = 16; o > 0; o >>= 1) s2 += __shfl_xor_sync(0xffffffffu, s2, o);
    if ((tid & 31) == 0) sh[tid >> 5] = s2;
    __syncthreads();
    float var = (sh[0] + sh[1] + sh[2] + sh[3]) / (float)E_;
    float scale = rsqrtf(var + EPS_);
#pragma unroll
    for (int i = 0; i < 3; i++) {
        int e = tid + i * 128;
        float hv = (v[i] - mu) * scale * w[e] + bb[e];
        g_hidden[row * E_ + e] = hv;
        __nv_bfloat16 h, l;
        split1(hv, h, l);
        a_hid_h[row * E_ + e] = h;
        a_hid_l[row * E_ + e] = l;
    }
}

// ---------------- generic predicated 64x64 fp32 GEMM (logits) ----------------
template <int EPI>
__global__ void __launch_bounds__(256) gemm_kernel(const float* __restrict__ A,
                                                   const float* __restrict__ W,
                                                   const float* __restrict__ bias,
                                                   float* __restrict__ C,
                                                   int M, int N, int K)
{
    const int BM = 64, BN = 64, BK = 16;
    __shared__ float As[BK][BM];
    __shared__ float Bs[BK][BN];
    int tid = threadIdx.x;
    int tx = tid & 15, ty = tid >> 4;
    int rowBase = blockIdx.y * BM, colBase = blockIdx.x * BN;
    float acc[4][4] = {};

    for (int k0 = 0; k0 < K; k0 += BK) {
#pragma unroll
        for (int i = 0; i < 4; i++) {
            int idx = tid + i * 256;
            int k = idx & 15, m = idx >> 4;
            int gr = rowBase + m, gc = k0 + k;
            As[k][m] = (gr < M && gc < K) ? A[(long)gr * K + gc] : 0.f;
        }
#pragma unroll
        for (int i = 0; i < 4; i++) {
            int idx = tid + i * 256;
            int k = idx & 15, nn = idx >> 4;
            int gr = colBase + nn, gc = k0 + k;
            Bs[k][nn] = (gr < N && gc < K) ? W[(long)gr * K + gc] : 0.f;
        }
        __syncthreads();
#pragma unroll
        for (int kk = 0; kk < BK; kk++) {
            float4 av = *reinterpret_cast<const float4*>(&As[kk][ty * 4]);
            float4 bv = *reinterpret_cast<const float4*>(&Bs[kk][tx * 4]);
            float a[4] = {av.x, av.y, av.z, av.w};
            float b[4] = {bv.x, bv.y, bv.z, bv.w};
#pragma unroll
            for (int i = 0; i < 4; i++)
#pragma unroll
                for (int j = 0; j < 4; j++)
                    acc[i][j] = fmaf(a[i], b[j], acc[i][j]);
        }
        __syncthreads();
    }

#pragma unroll
    for (int i = 0; i < 4; i++) {
        int r = rowBase + ty * 4 + i;
        if (r >= M) continue;
#pragma unroll
        for (int j = 0; j < 4; j++) {
            int c = colBase + tx * 4 + j;
            if (c >= N) continue;
            float v = acc[i][j] + (bias ? bias[c] : 0.f);
            if (EPI == 1) v = fmaxf(v, 0.f);
            if (EPI == 2) v += C[(long)r * N + c];
            C[(long)r * N + c] = v;
        }
    }
}

// ---------------- xproj split-K ----------------
__global__ void __launch_bounds__(256) xproj_partial_kernel(const float* __restrict__ A,
                                                            const float* __restrict__ W)
{
    const int BK = 16, KS = DI_ / SPK_;
    __shared__ float As[BK][64];
    __shared__ float Bs[BK][64];
    int tid = threadIdx.x;
    int tx = tid & 15, ty = tid >> 4;
    int rowBase = blockIdx.y * 64;
    int s = blockIdx.z;
    int kbase = s * KS;
    float acc[4][4] = {};

    for (int k0 = 0; k0 < KS; k0 += BK) {
#pragma unroll
        for (int i = 0; i < 4; i++) {
            int idx = tid + i * 256;
            int k = idx & 15, m = idx >> 4;
            As[k][m] = A[(long)(rowBase + m) * DI_ + kbase + k0 + k];
        }
#pragma unroll
        for (int i = 0; i < 4; i++) {
            int idx = tid + i * 256;
            int k = idx & 15, nn = idx >> 4;
            Bs[k][nn] = (nn < DBL_) ? W[(long)nn * DI_ + kbase + k0 + k] : 0.f;
        }
        __syncthreads();
#pragma unroll
        for (int kk = 0; kk < BK; kk++) {
            float4 av = *reinterpret_cast<const float4*>(&As[kk][ty * 4]);
            float4 bv = *reinterpret_cast<const float4*>(&Bs[kk][tx * 4]);
            float a[4] = {av.x, av.y, av.z, av.w};
            float b[4] = {bv.x, bv.y, bv.z, bv.w};
#pragma unroll
            for (int i = 0; i < 4; i++)
#pragma unroll
                for (int j = 0; j < 4; j++)
                    acc[i][j] = fmaf(a[i], b[j], acc[i][j]);
        }
        __syncthreads();
    }

#pragma unroll
    for (int i = 0; i < 4; i++) {
        int r = rowBase + ty * 4 + i;
#pragma unroll
        for (int j = 0; j < 4; j++) {
            int c = tx * 4 + j;
            if (c < DBL_)
                g_dblp[((long)s * M_ + r) * DBL_ + c] = acc[i][j];
        }
    }
}

__global__ void xproj_reduce_kernel()
{
    int idx = blockIdx.x * blockDim.x + threadIdx.x;
    if (idx >= M_ * DBL_) return;
    float v = 0.f;
#pragma unroll
    for (int s = 0; s < SPK_; s++) v += g_dblp[(long)s * M_ * DBL_ + idx];
    g_dbl[idx] = v;
}

// ---------------- causal depthwise conv + bias + silu ----------------
__global__ void conv_silu_kernel(const float* __restrict__ cw, const float* __restrict__ cb)
{
    int idx = blockIdx.x * blockDim.x + threadIdx.x;
    if (idx >= M_ * DI_) return;
    int d = idx % DI_;
    int bt = idx / DI_;
    int t = bt % T_;
    float acc = cb[d];
    const float* w = &cw[d * DC_];
#pragma unroll
    for (int k = 0; k < DC_; k++) {
        int tt = t - (DC_ - 1) + k;
        if (tt >= 0) acc = fmaf(w[k], g_xz[(long)(bt - t + tt) * 2 * DI_ + d], acc);
    }
    float sig = 1.f / (1.f + __expf(-acc));
    g_xc[idx] = acc * sig;
}

// ---------------- dt = softplus(dbl[:, :DR] @ dt_w^T + dt_b) ----------------
__global__ void __launch_bounds__(256) dt_kernel(const float* __restrict__ dtw,
                                                 const float* __restrict__ dtb)
{
    int row = blockIdx.x;
    int tid = threadIdx.x;
    __shared__ float dr[DR_];
    if (tid < DR_) dr[tid] = g_dbl[row * DBL_ + tid];
    __syncthreads();
#pragma unroll
    for (int c = 0; c < 3; c++) {
        int d = c * 256 + tid;
        float acc = dtb[d];
        const float* w = &dtw[d * DR_];
#pragma unroll
        for (int r = 0; r < DR_; r++) acc = fmaf(dr[r], w[r], acc);
        float sp = (acc > 20.f) ? acc : log1pf(__expf(acc));
        g_dt[row * DI_ + d] = sp;
    }
}

// ---------------- selective scan (+ y hi/lo) ----------------
__global__ void __launch_bounds__(256) scan_kernel(const float* __restrict__ Alog,
                                                   const float* __restrict__ Dp)
{
    int b = blockIdx.y;
    int tid = threadIdx.x;
    int d = blockIdx.x * 256 + tid;
    __shared__ float Bs[DS_], Cs[DS_];
    float Av[DS_], h[DS_];
#pragma unroll
    for (int s = 0; s < DS_; s++) {
        Av[s] = -__expf(Alog[d * DS_ + s]);
        h[s] = 0.f;
    }
    float Dv = Dp[d];
    for (int t = 0; t < T_; t++) {
        int row = b * T_ + t;
        if (tid < DS_)           Bs[tid]       = g_dbl[row * DBL_ + DR_ + tid];
        else if (tid < 2 * DS_)  Cs[tid - DS_] = g_dbl[row * DBL_ + DR_ + DS_ + (tid - DS_)];
        __syncthreads();
        float dtv = g_dt[row * DI_ + d];
        float xcv = g_xc[row * DI_ + d];
        float zv  = g_xz[(long)row * 2 * DI_ + DI_ + d];
        float dtx = dtv * xcv;
        float y = 0.f;
#pragma unroll
        for (int s = 0; s < DS_; s++) {
            float dA = __expf(dtv * Av[s]);
            h[s] = fmaf(dA, h[s], dtx * Bs[s]);
            y = fmaf(h[s], Cs[s], y);
        }
        y = fmaf(Dv, xcv, y);
        float sig = 1.f / (1.f + __expf(-zv));
        float yo = y * zv * sig;
        __nv_bfloat16 hh, ll;
        split1(yo, hh, ll);
        a_y_h[(long)row * DI_ + d] = hh;
        a_y_l[(long)row * DI_ + d] = ll;
        __syncthreads();
    }
}

// ---------------- attention (+ ctx hi/lo) ----------------
__global__ void __launch_bounds__(256) attn_kernel()
{
    int h = blockIdx.x;
    int b = blockIdx.y;
    int tid = threadIdx.x;
    __shared__ float qsh[T_ * HD_];
    __shared__ float p[L_];
    __shared__ float red[8];
    __shared__ float accs[4 * HD_];
    __shared__ float s_mx, s_inv;

#pragma unroll
    for (int i = 0; i < 8; i++) {
        int idx = tid + i * 256;
        int t = idx >> 6, d = idx & 63;
        qsh[idx] = g_qh[(long)(b * T_ + t) * E_ + h * HD_ + d];
    }
    __syncthreads();

    const float* kr = &g_kh[((long)b * L_ + tid) * E_ + h * HD_];
    const float* vb = &g_vh[((long)b * L_) * E_ + h * HD_];
    int lane = tid & 31, wid = tid >> 5;
    int dd = tid & 63, grp = tid >> 6;

    for (int t = 0; t < T_; t++) {
        const float* qr = &qsh[t * HD_];
        float sc = 0.f;
#pragma unroll
        for (int d = 0; d < HD_; d++) sc = fmaf(qr[d], kr[d], sc);
        sc *= 0.125f;

        float m = sc;
#pragma unroll
        for (int o = 16; o > 0; o >>= 1) m = fmaxf(m, __shfl_xor_sync(0xffffffffu, m, o));
        if (lane == 0) red[wid] = m;
        __syncthreads();
        if (tid == 0) {
            float mm = red[0];
#pragma unroll
            for (int i = 1; i < 8; i++) mm = fmaxf(mm, red[i]);
            s_mx = mm;
        }
        __syncthreads();
        float e = __expf(sc - s_mx);
        p[tid] = e;
        float ss = e;
#pragma unroll
        for (int o = 16; o > 0; o >>= 1) ss += __shfl_xor_sync(0xffffffffu, ss, o);
        if (lane == 0) red[wid] = ss;
        __syncthreads();
        if (tid == 0) {
            float s = 0.f;
#pragma unroll
            for (int i = 0; i < 8; i++) s += red[i];
            s_inv = 1.f / s;
        }
        __syncthreads();

        float part = 0.f;
        const float* vrow = vb + (long)(grp * 64) * E_ + dd;
#pragma unroll
        for (int s = 0; s < 64; s++) part = fmaf(p[grp * 64 + s], vrow[(long)s * E_], part);
        accs[grp * HD_ + dd] = part;
        __syncthreads();
        if (tid < HD_) {
            float v = (accs[tid] + accs[HD_ + tid] + accs[2 * HD_ + tid] + accs[3 * HD_ + tid]) * s_inv;
            __nv_bfloat16 hh, ll;
            split1(v, hh, ll);
            long off = (long)(b * T_ + t) * E_ + h * HD_ + tid;
            a_ctx_h[off] = hh;
            a_ctx_l[off] = ll;
        }
        __syncthreads();
    }
}

// ---------------- host ----------------
#define SMEM_MMA(BN) ((128 + (BN)) * PADK * 2 * 2 * 2)  /* elems*2stages*2B */

extern "C" void kernel_launch(void* const* d_in, const int* in_sizes, int n_in,
                              void* d_out, int out_size)
{
    (void)in_sizes; (void)n_in; (void)out_size;
    const float* enc      = (const float*)d_in[0];
    const float* qe       = (const float*)d_in[1];
    const float* pe       = (const float*)d_in[2];
    const float* m_norm_w = (const float*)d_in[3];
    const float* m_in_w   = (const float*)d_in[4];
    const float* m_conv_w = (const float*)d_in[5];
    const float* m_conv_b = (const float*)d_in[6];
    const float* m_xproj_w= (const float*)d_in[7];
    const float* m_dt_w   = (const float*)d_in[8];
    const float* m_dt_b   = (const float*)d_in[9];
    const float* m_Alog   = (const float*)d_in[10];
    const float* m_D      = (const float*)d_in[11];
    const float* m_out_w  = (const float*)d_in[12];
    const float* rms_w    = (const float*)d_in[13];
    const float* wq = (const float*)d_in[14];
    const float* bq = (const float*)d_in[15];
    const float* wk = (const float*)d_in[16];
    const float* bk = (const float*)d_in[17];
    const float* wv = (const float*)d_in[18];
    const float* bv = (const float*)d_in[19];
    const float* wo = (const float*)d_in[20];
    const float* bo = (const float*)d_in[21];
    const float* ln1_w = (const float*)d_in[22];
    const float* ln1_b = (const float*)d_in[23];
    const float* ffn_w1 = (const float*)d_in[24];
    const float* ffn_b1 = (const float*)d_in[25];
    const float* ffn_w2 = (const float*)d_in[26];
    const float* ffn_b2 = (const float*)d_in[27];
    const float* ln2_w = (const float*)d_in[28];
    const float* ln2_b = (const float*)d_in[29];
    const float* out_w = (const float*)d_in[30];
    const float* out_b = (const float*)d_in[31];
    float* out = (float*)d_out;

    // resolve device-global addresses
    float *p_hidden, *p_xz, *p_xc, *p_qh, *p_kh, *p_vh, *p_resid;
    cudaGetSymbolAddress((void**)&p_hidden, g_hidden);
    cudaGetSymbolAddress((void**)&p_resid,  g_resid);
    cudaGetSymbolAddress((void**)&p_xz,     g_xz);
    cudaGetSymbolAddress((void**)&p_xc,     g_xc);
    cudaGetSymbolAddress((void**)&p_qh,     g_qh);
    cudaGetSymbolAddress((void**)&p_kh,     g_kh);
    cudaGetSymbolAddress((void**)&p_vh,     g_vh);

    __nv_bfloat16 *pw_inw_h, *pw_inw_l, *pw_outw_h, *pw_outw_l;
    __nv_bfloat16 *pw_q_h, *pw_q_l, *pw_k_h, *pw_k_l, *pw_v_h, *pw_v_l, *pw_o_h, *pw_o_l;
    __nv_bfloat16 *pw_f1_h, *pw_f1_l, *pw_f2_h, *pw_f2_l;
    __nv_bfloat16 *pa_hid_h, *pa_hid_l, *pa_y_h, *pa_y_l, *pa_ctx_h, *pa_ctx_l;
    __nv_bfloat16 *pa_ffn_h, *pa_ffn_l, *pa_enc_h, *pa_enc_l;
    cudaGetSymbolAddress((void**)&pw_inw_h, w_inw_h);   cudaGetSymbolAddress((void**)&pw_inw_l, w_inw_l);
    cudaGetSymbolAddress((void**)&pw_outw_h, w_outw_h); cudaGetSymbolAddress((void**)&pw_outw_l, w_outw_l);
    cudaGetSymbolAddress((void**)&pw_q_h, w_q_h);   cudaGetSymbolAddress((void**)&pw_q_l, w_q_l);
    cudaGetSymbolAddress((void**)&pw_k_h, w_k_h);   cudaGetSymbolAddress((void**)&pw_k_l, w_k_l);
    cudaGetSymbolAddress((void**)&pw_v_h, w_v_h);   cudaGetSymbolAddress((void**)&pw_v_l, w_v_l);
    cudaGetSymbolAddress((void**)&pw_o_h, w_o_h);   cudaGetSymbolAddress((void**)&pw_o_l, w_o_l);
    cudaGetSymbolAddress((void**)&pw_f1_h, w_f1_h); cudaGetSymbolAddress((void**)&pw_f1_l, w_f1_l);
    cudaGetSymbolAddress((void**)&pw_f2_h, w_f2_h); cudaGetSymbolAddress((void**)&pw_f2_l, w_f2_l);
    cudaGetSymbolAddress((void**)&pa_hid_h, a_hid_h); cudaGetSymbolAddress((void**)&pa_hid_l, a_hid_l);
    cudaGetSymbolAddress((void**)&pa_y_h, a_y_h);     cudaGetSymbolAddress((void**)&pa_y_l, a_y_l);
    cudaGetSymbolAddress((void**)&pa_ctx_h, a_ctx_h); cudaGetSymbolAddress((void**)&pa_ctx_l, a_ctx_l);
    cudaGetSymbolAddress((void**)&pa_ffn_h, a_ffn_h); cudaGetSymbolAddress((void**)&pa_ffn_l, a_ffn_l);
    cudaGetSymbolAddress((void**)&pa_enc_h, a_enc_h); cudaGetSymbolAddress((void**)&pa_enc_l, a_enc_l);

    cudaFuncSetAttribute(mma_gemm<128, 0>, cudaFuncAttributeMaxDynamicSharedMemorySize, SMEM_MMA(128));
    cudaFuncSetAttribute(mma_gemm<128, 3>, cudaFuncAttributeMaxDynamicSharedMemorySize, SMEM_MMA(128));
    cudaFuncSetAttribute(mma_gemm<64, 0>,  cudaFuncAttributeMaxDynamicSharedMemorySize, SMEM_MMA(64));
    cudaFuncSetAttribute(mma_gemm<64, 2>,  cudaFuncAttributeMaxDynamicSharedMemorySize, SMEM_MMA(64));

    // weight + enc conversions (deterministic per launch)
    {
        const int TB = 256;
        convert_hl<<<(ND_ * 2 * DI_ * E_ / 4 + TB - 1) / TB, TB>>>(m_in_w,  pw_inw_h,  pw_inw_l,  ND_ * 2 * DI_ * E_ / 4);
        convert_hl<<<(ND_ * E_ * DI_ / 4 + TB - 1) / TB, TB>>>(m_out_w, pw_outw_h, pw_outw_l, ND_ * E_ * DI_ / 4);
        convert_hl<<<(E_ * E_ / 4 + TB - 1) / TB, TB>>>(wq, pw_q_h, pw_q_l, E_ * E_ / 4);
        convert_hl<<<(E_ * E_ / 4 + TB - 1) / TB, TB>>>(wk, pw_k_h, pw_k_l, E_ * E_ / 4);
        convert_hl<<<(E_ * E_ / 4 + TB - 1) / TB, TB>>>(wv, pw_v_h, pw_v_l, E_ * E_ / 4);
        convert_hl<<<(E_ * E_ / 4 + TB - 1) / TB, TB>>>(wo, pw_o_h, pw_o_l, E_ * E_ / 4);
        convert_hl<<<(HID_ * E_ / 4 + TB - 1) / TB, TB>>>(ffn_w1, pw_f1_h, pw_f1_l, HID_ * E_ / 4);
        convert_hl<<<(E_ * HID_ / 4 + TB - 1) / TB, TB>>>(ffn_w2, pw_f2_h, pw_f2_l, E_ * HID_ / 4);
        convert_hl<<<(ML_ * E_ / 4 + TB - 1) / TB, TB>>>(enc, pa_enc_h, pa_enc_l, ML_ * E_ / 4);
    }

    init_kernel<<<(M_ * E_ + 255) / 256, 256>>>(qe, pe);

    for (int n = 0; n < ND_; n++) {
        add_rmsnorm_kernel<<<M_, 128>>>(m_norm_w + n * E_);
        // xz = hidden @ in_w^T   [2048 x 1536, K=384]
        mma_gemm<128, 0><<<dim3(2 * DI_ / 128, M_ / 128), 256, SMEM_MMA(128)>>>(
            pa_hid_h, pa_hid_l,
            pw_inw_h + (long)n * 2 * DI_ * E_, pw_inw_l + (long)n * 2 * DI_ * E_,
            nullptr, p_xz, nullptr, nullptr, M_, 2 * DI_, E_);
        conv_silu_kernel<<<(M_ * DI_ + 255) / 256, 256>>>(m_conv_w + (long)n * DI_ * DC_,
                                                          m_conv_b + n * DI_);
        xproj_partial_kernel<<<dim3(1, M_ / 64, SPK_), 256>>>(p_xc,
            m_xproj_w + (long)n * DBL_ * DI_);
        xproj_reduce_kernel<<<(M_ * DBL_ + 255) / 256, 256>>>();
        dt_kernel<<<M_, 256>>>(m_dt_w + (long)n * DI_ * DR_, m_dt_b + n * DI_);
        scan_kernel<<<dim3(DI_ / 256, B_), 256>>>(m_Alog + (long)n * DI_ * DS_, m_D + n * DI_);
        // hidden = y @ out_w^T   [2048 x 384, K=768]
        mma_gemm<64, 0><<<dim3(E_ / 64, M_ / 128), 256, SMEM_MMA(64)>>>(
            pa_y_h, pa_y_l,
            pw_outw_h + (long)n * E_ * DI_, pw_outw_l + (long)n * E_ * DI_,
            nullptr, p_hidden, nullptr, nullptr, M_, E_, DI_);
    }

    add_rmsnorm_kernel<<<M_, 128>>>(rms_w);

    mma_gemm<64, 0><<<dim3(E_ / 64, M_ / 128), 256, SMEM_MMA(64)>>>(
        pa_hid_h, pa_hid_l, pw_q_h, pw_q_l, bq, p_qh, nullptr, nullptr, M_, E_, E_);
    mma_gemm<128, 0><<<dim3(E_ / 128, ML_ / 128), 256, SMEM_MMA(128)>>>(
        pa_enc_h, pa_enc_l, pw_k_h, pw_k_l, bk, p_kh, nullptr, nullptr, ML_, E_, E_);
    mma_gemm<128, 0><<<dim3(E_ / 128, ML_ / 128), 256, SMEM_MMA(128)>>>(
        pa_enc_h, pa_enc_l, pw_v_h, pw_v_l, bv, p_vh, nullptr, nullptr, ML_, E_, E_);

    attn_kernel<<<dim3(H_, B_), 256>>>();

    // resid += ctx @ wo^T + bo
    mma_gemm<64, 2><<<dim3(E_ / 64, M_ / 128), 256, SMEM_MMA(64)>>>(
        pa_ctx_h, pa_ctx_l, pw_o_h, pw_o_l, bo, p_resid, nullptr, nullptr, M_, E_, E_);

    layernorm_kernel<<<M_, 128>>>(ln1_w, ln1_b);
    // ffn = relu(hidden @ w1^T + b1) -> bf16 hi/lo
    mma_gemm<128, 3><<<dim3(HID_ / 128, M_ / 128), 256, SMEM_MMA(128)>>>(
        pa_hid_h, pa_hid_l, pw_f1_h, pw_f1_l, ffn_b1, nullptr, pa_ffn_h, pa_ffn_l, M_, HID_, E_);
    // resid += ffn @ w2^T + b2
    mma_gemm<64, 2><<<dim3(E_ / 64, M_ / 128), 256, SMEM_MMA(64)>>>(
        pa_ffn_h, pa_ffn_l, pw_f2_h, pw_f2_l, ffn_b2, p_resid, nullptr, nullptr, M_, E_, HID_);
    layernorm_kernel<<<M_, 128>>>(ln2_w, ln2_b);

    gemm_kernel<0><<<dim3((V_ + 63) / 64, M_ / 64), 256>>>(p_hidden, out_w, out_b, out,
                                                           M_, V_, E_);
}